// round 13
// baseline (speedup 1.0000x reference)
#include <cuda_runtime.h>
#include <cuda_fp16.h>
#include <math.h>
#include <cstdint>

// ---------------------------------------------------------------- constants
#define BATCH 2
#define SEQ 2048
#define DMODEL 2048
#define DINNER 4096
#define DSTATE 16
#define M_TOT (BATCH*SEQ)          // 4096

// GEMM tiling: 128x128 CTA tile, 128 threads (4 warps x 64x64), KC=64, 3 stages
#define MT 128
#define NT 128
#define KC 64
#define STAGES 3
#define ROW_BYTES 128                              // 64 halves, SW128 swizzled
#define STAGE_ROWS 256                             // A (128) + B (128)
#define STAGE_BYTES (STAGE_ROWS * ROW_BYTES)       // 32768
#define SMEM_BYTES (STAGES * STAGE_BYTES)          // 98304

// standard SW128 swizzle: bits[4:6] ^= bits[7:9]
#define SWZ(off) ((off) ^ (((off) >> 3) & 0x70))

// ---------------------------------------------------------------- scratch
__device__ __align__(1024) float  g_xi[(size_t)M_TOT * DINNER];
__device__ __align__(1024) __half g_x[(size_t)M_TOT * DMODEL];
__device__ __align__(1024) __half g_win[(size_t)2*DINNER * DMODEL];
__device__ __align__(1024) __half g_wout[(size_t)DMODEL * DINNER];
__device__ __align__(1024) __half g_gate[(size_t)M_TOT * DINNER];
__device__ float g_a[M_TOT * DSTATE];
__device__ float g_u[M_TOT * DSTATE];
__device__ float g_scale[M_TOT];

static __device__ __forceinline__ float sigmoidf_(float v) {
    return 1.0f / (1.0f + expf(-v));
}

__device__ __forceinline__ uint32_t smem_u32(const void* p) {
    uint32_t a;
    asm("{ .reg .u64 t; cvta.to.shared.u64 t, %1; cvt.u32.u64 %0, t; }" : "=r"(a) : "l"(p));
    return a;
}

#define CP_ASYNC_16(saddr, gptr) \
    asm volatile("cp.async.cg.shared.global [%0], [%1], 16;" :: "r"(saddr), "l"(gptr))
#define CP_COMMIT() asm volatile("cp.async.commit_group;" ::: "memory")
#define CP_WAITN(n) asm volatile("cp.async.wait_group %0;" :: "n"(n) : "memory")

#define LDMATRIX_X4(r0,r1,r2,r3, addr) \
    asm volatile("ldmatrix.sync.aligned.m8n8.x4.shared.b16 {%0,%1,%2,%3}, [%4];" \
                 : "=r"(r0), "=r"(r1), "=r"(r2), "=r"(r3) : "r"(addr))

#define MMA_F16(c, a0,a1,a2,a3, b0,b1) \
    asm volatile("mma.sync.aligned.m16n8k16.row.col.f32.f16.f16.f32 " \
                 "{%0,%1,%2,%3}, {%4,%5,%6,%7}, {%8,%9}, {%0,%1,%2,%3};" \
                 : "+f"((c)[0]), "+f"((c)[1]), "+f"((c)[2]), "+f"((c)[3]) \
                 : "r"(a0), "r"(a1), "r"(a2), "r"(a3), "r"(b0), "r"(b1))

// ---------------------------------------------------------------- preprocessing
__global__ void __launch_bounds__(256) cvt_f16(const float* __restrict__ in,
                                               __half* __restrict__ o,
                                               int n4) {
    int i = blockIdx.x * 256 + threadIdx.x;
    if (i >= n4) return;
    float4 v = ((const float4*)in)[i];
    ((__half2*)o)[2*i]   = __halves2half2(__float2half(v.x), __float2half(v.y));
    ((__half2*)o)[2*i+1] = __halves2half2(__float2half(v.z), __float2half(v.w));
}

// ---------------------------------------------------------------- mma GEMM
// 128 threads, 4 warps x (64x64 warp tile), 128x128 CTA tile, 2 CTAs/SM, KC=64.
// MODE 0: n<4096 -> g_xi fp32 ; n>=4096 -> sigmoid -> g_gate fp16
// MODE 1: out[m,n] = g_scale[m]*acc
template <int MODE, int K>
__global__ void __launch_bounds__(128, 2) gemm_mma(const __half* __restrict__ A,
                                                   const __half* __restrict__ B,
                                                   float* __restrict__ out) {
    constexpr int NIT = K / KC;

    extern __shared__ char smem[];
    const uint32_t sb = smem_u32(smem);

    const int tid  = threadIdx.x;
    const int lane = tid & 31;
    const int wid  = tid >> 5;        // 0..3
    const int warpM = wid & 1;        // 2 warps in M (64 rows each)
    const int warpN = wid >> 1;       // 2 warps in N (64 cols each)
    const int m0 = blockIdx.y * MT;
    const int n0 = blockIdx.x * NT;

    // cp.async: 2048 16B-chunks per stage, 16 per thread (swizzled dst)
    uint32_t sOff[16];
#pragma unroll
    for (int i = 0; i < 16; ++i) {
        int c   = tid + i * 128;       // 0..2047
        int row = c >> 3;              // 0..255 (8 chunks per 128B row)
        uint32_t off = (uint32_t)row * ROW_BYTES + (c & 7) * 16;
        sOff[i] = SWZ(off);
    }

    // ldmatrix base offsets (kk=0); kk -> XOR kk*32 (swizzle is row-only)
    uint32_t aOff[4], bOff[4];
#pragma unroll
    for (int mi = 0; mi < 4; ++mi) {
        int r = warpM * 64 + mi * 16 + (lane & 15);
        uint32_t off = (uint32_t)r * ROW_BYTES + (lane >> 4) * 16;
        aOff[mi] = SWZ(off);
    }
#pragma unroll
    for (int nh = 0; nh < 4; ++nh) {
        int r = 128 + warpN * 64 + nh * 16 + ((lane >> 4) & 1) * 8 + (lane & 7);
        uint32_t off = (uint32_t)r * ROW_BYTES + ((lane >> 3) & 1) * 16;
        bOff[nh] = SWZ(off);
    }

    float acc[4][8][4];
#pragma unroll
    for (int mi = 0; mi < 4; ++mi)
#pragma unroll
        for (int ni = 0; ni < 8; ++ni)
#pragma unroll
            for (int e = 0; e < 4; ++e) acc[mi][ni][e] = 0.f;

    auto issue_load = [&](int j, int slot) {
        const int k0 = j * KC;
        const uint32_t stBase = sb + slot * STAGE_BYTES;
#pragma unroll
        for (int i = 0; i < 16; ++i) {
            int c   = tid + i * 128;
            int row = c >> 3;
            int off = (c & 7) * 8;     // halves within row
            const __half* g;
            if (i < 8) g = A + (size_t)(m0 + row)       * K + k0 + off;
            else       g = B + (size_t)(n0 + row - 128) * K + k0 + off;
            CP_ASYNC_16(stBase + sOff[i], g);
        }
        CP_COMMIT();
    };

    issue_load(0, 0);
    issue_load(1, 1);

    int slot = 0;
    for (int j = 0; j < NIT; ++j) {
        CP_WAITN(1);                   // load j landed; j+1 may still fly
        __syncthreads();
        const int jn = j + 2;
        if (jn < NIT) {
            int sl = slot + 2; if (sl >= STAGES) sl -= STAGES;
            issue_load(jn, sl);
        } else {
            CP_COMMIT();               // keep group counting aligned
        }

        const uint32_t stBase = sb + slot * STAGE_BYTES;

#pragma unroll
        for (int kk = 0; kk < 4; ++kk) {
            const uint32_t kx = kk * 32;
            uint32_t bf[8][2];
#pragma unroll
            for (int nh = 0; nh < 4; ++nh) {
                uint32_t r0, r1, r2, r3;
                LDMATRIX_X4(r0, r1, r2, r3, stBase + (bOff[nh] ^ kx));
                bf[2*nh][0] = r0;   bf[2*nh][1] = r1;
                bf[2*nh+1][0] = r2; bf[2*nh+1][1] = r3;
            }
            uint32_t a[4][4];
#pragma unroll
            for (int mi = 0; mi < 4; ++mi)
                LDMATRIX_X4(a[mi][0], a[mi][1], a[mi][2], a[mi][3],
                            stBase + (aOff[mi] ^ kx));
#pragma unroll
            for (int mi = 0; mi < 4; ++mi)
#pragma unroll
                for (int ni = 0; ni < 8; ++ni)
                    MMA_F16(acc[mi][ni], a[mi][0], a[mi][1], a[mi][2], a[mi][3],
                            bf[ni][0], bf[ni][1]);
        }
        if (++slot >= STAGES) slot = 0;
    }

    // ------------------------------------------------------------ epilogue
    const int gid = lane >> 2;
    const int tig = lane & 3;

#pragma unroll
    for (int mi = 0; mi < 4; ++mi) {
        int rbase = m0 + warpM * 64 + mi * 16 + gid;
#pragma unroll
        for (int half = 0; half < 2; ++half) {
            int m = rbase + half * 8;
            float sc = (MODE == 1) ? g_scale[m] : 0.f;
#pragma unroll
            for (int ni = 0; ni < 8; ++ni) {
                int n = n0 + warpN * 64 + ni * 8 + tig * 2;
                float v0 = acc[mi][ni][half * 2 + 0];
                float v1 = acc[mi][ni][half * 2 + 1];
                if (MODE == 0) {
                    if (n0 < DINNER) {
                        *(float2*)&g_xi[(size_t)m * DINNER + n] = make_float2(v0, v1);
                    } else {
                        float s0 = sigmoidf_(v0), s1 = sigmoidf_(v1);
                        size_t idx = (size_t)m * DINNER + (n - DINNER);
                        *(__half2*)&g_gate[idx] =
                            __halves2half2(__float2half(s0), __float2half(s1));
                    }
                } else {
                    *(float2*)&out[(size_t)m * DMODEL + n] = make_float2(sc * v0, sc * v1);
                }
            }
        }
    }
}

// ---------------------------------------------------------------- conv + dt
__global__ void __launch_bounds__(256) conv_dt_kernel(const float* __restrict__ conv_w,
                                                      const float* __restrict__ conv_b,
                                                      const float* __restrict__ W_dt,
                                                      const float* __restrict__ b_dt) {
    const int warp = threadIdx.x >> 5;
    const int lane = threadIdx.x & 31;
    const int m = blockIdx.x * 8 + warp;
    const int s = m & (SEQ - 1);

    float acc[16];
#pragma unroll
    for (int i = 0; i < 16; ++i) acc[i] = 0.f;

    const float* xi_row = g_xi + (size_t)m * DINNER;

    for (int it = 0; it < DINNER / 128; ++it) {
        int e = it * 128 + lane * 4;
        float4 w0 = *(const float4*)(conv_w + (size_t)(e + 0) * 4);
        float4 w1 = *(const float4*)(conv_w + (size_t)(e + 1) * 4);
        float4 w2 = *(const float4*)(conv_w + (size_t)(e + 2) * 4);
        float4 w3 = *(const float4*)(conv_w + (size_t)(e + 3) * 4);
        float4 cb = *(const float4*)(conv_b + e);

        float4 xk[4];
#pragma unroll
        for (int k = 0; k < 4; ++k) {
            int d = 3 - k;
            if (s - d >= 0) xk[k] = *(const float4*)(xi_row - (size_t)d * DINNER + e);
            else            xk[k] = make_float4(0.f, 0.f, 0.f, 0.f);
        }
        float4 v;
        v.x = fmaf(w0.x, xk[0].x, fmaf(w0.y, xk[1].x, fmaf(w0.z, xk[2].x, fmaf(w0.w, xk[3].x, cb.x))));
        v.y = fmaf(w1.x, xk[0].y, fmaf(w1.y, xk[1].y, fmaf(w1.z, xk[2].y, fmaf(w1.w, xk[3].y, cb.y))));
        v.z = fmaf(w2.x, xk[0].z, fmaf(w2.y, xk[1].z, fmaf(w2.z, xk[2].z, fmaf(w2.w, xk[3].z, cb.z))));
        v.w = fmaf(w3.x, xk[0].w, fmaf(w3.y, xk[1].w, fmaf(w3.z, xk[2].w, fmaf(w3.w, xk[3].w, cb.w))));

        float4 xs;
        xs.x = v.x * sigmoidf_(v.x);
        xs.y = v.y * sigmoidf_(v.y);
        xs.z = v.z * sigmoidf_(v.z);
        xs.w = v.w * sigmoidf_(v.w);

        if (it == 0 && lane < 4) {
            g_u[m * DSTATE + e + 0] = xs.x;
            g_u[m * DSTATE + e + 1] = xs.y;
            g_u[m * DSTATE + e + 2] = xs.z;
            g_u[m * DSTATE + e + 3] = xs.w;
        }
#pragma unroll
        for (int i = 0; i < 16; ++i) {
            float4 wd = *(const float4*)(W_dt + (size_t)i * DINNER + e);
            acc[i] = fmaf(xs.x, wd.x, acc[i]);
            acc[i] = fmaf(xs.y, wd.y, acc[i]);
            acc[i] = fmaf(xs.z, wd.z, acc[i]);
            acc[i] = fmaf(xs.w, wd.w, acc[i]);
        }
    }
#pragma unroll
    for (int i = 0; i < 16; ++i) {
#pragma unroll
        for (int off = 16; off > 0; off >>= 1)
            acc[i] += __shfl_xor_sync(0xffffffffu, acc[i], off);
    }
    if (lane == 0) {
#pragma unroll
        for (int i = 0; i < 16; ++i) {
            float z = acc[i] + b_dt[i];
            float sp = (z > 20.f) ? z : log1pf(expf(z));
            g_a[m * DSTATE + i] = 1.0f + sp;
        }
    }
}

// ---------------------------------------------------------------- scan
__global__ void __launch_bounds__(512) scan_kernel(const float* __restrict__ A_log) {
    const int b = blockIdx.x;
    const int tid = threadIdx.x;
    const int chunk = tid >> 4;
    const int j = tid & 15;
    const int t0 = chunk * 64;

    __shared__ float sP[32][16];
    __shared__ float sQ[32][16];
    __shared__ float sH[32][16];

    const float* a = g_a + (size_t)b * SEQ * DSTATE;
    const float* u = g_u + (size_t)b * SEQ * DSTATE;

    float P = 1.f, q = 0.f;
    for (int i = 0; i < 64; ++i) {
        float av = a[(t0 + i) * DSTATE + j];
        float uv = u[(t0 + i) * DSTATE + j];
        q = fmaf(q, av, uv);
        P *= av;
    }
    sP[chunk][j] = P;
    sQ[chunk][j] = q;
    __syncthreads();

    if (tid < 16) {
        float h = 0.f;
        for (int k = 0; k < 32; ++k) {
            sH[k][tid] = h;
            h = fmaf(sP[k][tid], h, sQ[k][tid]);
        }
    }
    __syncthreads();

    const float Aj = -expf(A_log[j]);
    float h = sH[chunk][j];
    for (int i = 0; i < 64; ++i) {
        int t = t0 + i;
        float av = a[t * DSTATE + j];
        float uv = u[t * DSTATE + j];
        h = fmaf(h, av, uv);
        float c = Aj * h;
        c += __shfl_xor_sync(0xffffffffu, c, 8, 16);
        c += __shfl_xor_sync(0xffffffffu, c, 4, 16);
        c += __shfl_xor_sync(0xffffffffu, c, 2, 16);
        c += __shfl_xor_sync(0xffffffffu, c, 1, 16);
        if (j == 0) g_scale[b * SEQ + t] = c * (float)DINNER;
    }
}

// ---------------------------------------------------------------- host
extern "C" void kernel_launch(void* const* d_in, const int* in_sizes, int n_in,
                              void* d_out, int out_size) {
    const float* x      = (const float*)d_in[0];
    const float* W_in   = (const float*)d_in[1];
    const float* conv_w = (const float*)d_in[2];
    const float* conv_b = (const float*)d_in[3];
    const float* W_dt   = (const float*)d_in[4];
    const float* b_dt   = (const float*)d_in[5];
    const float* A_log  = (const float*)d_in[6];
    const float* W_out  = (const float*)d_in[7];
    float* out = (float*)d_out;
    (void)in_sizes; (void)n_in; (void)out_size;

    void *px, *pwi, *pwo, *pg;
    cudaGetSymbolAddress(&px, g_x);
    cudaGetSymbolAddress(&pwi, g_win);
    cudaGetSymbolAddress(&pwo, g_wout);
    cudaGetSymbolAddress(&pg, g_gate);

    cudaFuncSetAttribute(gemm_mma<0, DMODEL>, cudaFuncAttributeMaxDynamicSharedMemorySize, SMEM_BYTES);
    cudaFuncSetAttribute(gemm_mma<1, DINNER>, cudaFuncAttributeMaxDynamicSharedMemorySize, SMEM_BYTES);

    // preprocessing: fp32 -> fp16 conversions
    cvt_f16<<<(M_TOT * DMODEL / 4 + 255) / 256, 256>>>(x, (__half*)px, M_TOT * DMODEL / 4);
    cvt_f16<<<(2 * DINNER * DMODEL / 4 + 255) / 256, 256>>>(W_in, (__half*)pwi, 2 * DINNER * DMODEL / 4);
    cvt_f16<<<(DMODEL * DINNER / 4 + 255) / 256, 256>>>(W_out, (__half*)pwo, DMODEL * DINNER / 4);

    // GEMM1: xz = x @ W_in^T  (M=4096, N=8192, K=2048)
    gemm_mma<0, DMODEL><<<dim3(2 * DINNER / NT, M_TOT / MT), 128, SMEM_BYTES>>>(
        (const __half*)px, (const __half*)pwi, nullptr);

    // conv + silu + dt
    conv_dt_kernel<<<M_TOT / 8, 256>>>(conv_w, conv_b, W_dt, b_dt);
    // selective scan
    scan_kernel<<<BATCH, 512>>>(A_log);

    // GEMM2: out = scale * (sigmoid(gate) @ W_out^T)  (M=4096, N=2048, K=4096)
    gemm_mma<1, DINNER><<<dim3(DMODEL / NT, M_TOT / MT), 128, SMEM_BYTES>>>(
        (const __half*)pg, (const __half*)pwo, out);
}

// round 14
// speedup vs baseline: 1.0033x; 1.0033x over previous
#include <cuda_runtime.h>
#include <cuda_fp16.h>
#include <math.h>
#include <cstdint>

// ---------------------------------------------------------------- constants
#define BATCH 2
#define SEQ 2048
#define DMODEL 2048
#define DINNER 4096
#define DSTATE 16
#define M_TOT (BATCH*SEQ)          // 4096

// GEMM tiling (R12 champion): 128x128 CTA, 128 thr (4 warps x 64x64), KC=32, 5 stages
#define MT 128
#define NT 128
#define KC 32
#define STAGES 5
#define ROW_BYTES 64                               // 32 halves, swizzled
#define STAGE_ROWS 256                             // A (128) + B (128)
#define STAGE_BYTES (STAGE_ROWS * ROW_BYTES)       // 16384
#define SMEM_BYTES (STAGES * STAGE_BYTES)          // 81920

// swizzle: chunk(16B, bits[4:5]) ^= (row>>1)&3  (row stride 64B)
#define SWZ(off) ((off) ^ (((off) >> 3) & 0x30))

// ---------------------------------------------------------------- scratch
__device__ __align__(1024) __half g_xi[(size_t)M_TOT * DINNER];    // fp16 now
__device__ __align__(1024) __half g_x[(size_t)M_TOT * DMODEL];
__device__ __align__(1024) __half g_win[(size_t)2*DINNER * DMODEL];
__device__ __align__(1024) __half g_wout[(size_t)DMODEL * DINNER];
__device__ __align__(1024) __half g_gate[(size_t)M_TOT * DINNER];
__device__ float g_a[M_TOT * DSTATE];
__device__ float g_u[M_TOT * DSTATE];
__device__ float g_scale[M_TOT];

static __device__ __forceinline__ float sigmoidf_(float v) {
    return 1.0f / (1.0f + expf(-v));
}

__device__ __forceinline__ uint32_t smem_u32(const void* p) {
    uint32_t a;
    asm("{ .reg .u64 t; cvta.to.shared.u64 t, %1; cvt.u32.u64 %0, t; }" : "=r"(a) : "l"(p));
    return a;
}

#define CP_ASYNC_16(saddr, gptr) \
    asm volatile("cp.async.cg.shared.global [%0], [%1], 16;" :: "r"(saddr), "l"(gptr))
#define CP_COMMIT() asm volatile("cp.async.commit_group;" ::: "memory")
#define CP_WAITN(n) asm volatile("cp.async.wait_group %0;" :: "n"(n) : "memory")

#define LDMATRIX_X4(r0,r1,r2,r3, addr) \
    asm volatile("ldmatrix.sync.aligned.m8n8.x4.shared.b16 {%0,%1,%2,%3}, [%4];" \
                 : "=r"(r0), "=r"(r1), "=r"(r2), "=r"(r3) : "r"(addr))

#define MMA_F16(c, a0,a1,a2,a3, b0,b1) \
    asm volatile("mma.sync.aligned.m16n8k16.row.col.f32.f16.f16.f32 " \
                 "{%0,%1,%2,%3}, {%4,%5,%6,%7}, {%8,%9}, {%0,%1,%2,%3};" \
                 : "+f"((c)[0]), "+f"((c)[1]), "+f"((c)[2]), "+f"((c)[3]) \
                 : "r"(a0), "r"(a1), "r"(a2), "r"(a3), "r"(b0), "r"(b1))

// ---------------------------------------------------------------- preprocessing
__global__ void __launch_bounds__(256) cvt_f16(const float* __restrict__ in,
                                               __half* __restrict__ o,
                                               int n4) {
    int i = blockIdx.x * 256 + threadIdx.x;
    if (i >= n4) return;
    float4 v = ((const float4*)in)[i];
    ((__half2*)o)[2*i]   = __halves2half2(__float2half(v.x), __float2half(v.y));
    ((__half2*)o)[2*i+1] = __halves2half2(__float2half(v.z), __float2half(v.w));
}

// ---------------------------------------------------------------- mma GEMM
// 128 threads, 4 warps x (64x64 warp tile), 128x128 CTA tile, 2 CTAs/SM.
// MODE 0: n<4096 -> g_xi fp16 ; n>=4096 -> sigmoid -> g_gate fp16
// MODE 1: out[m,n] = g_scale[m]*acc
template <int MODE, int K>
__global__ void __launch_bounds__(128, 2) gemm_mma(const __half* __restrict__ A,
                                                   const __half* __restrict__ B,
                                                   float* __restrict__ out) {
    constexpr int NIT = K / KC;

    extern __shared__ char smem[];
    const uint32_t sb = smem_u32(smem);

    const int tid  = threadIdx.x;
    const int lane = tid & 31;
    const int wid  = tid >> 5;        // 0..3
    const int warpM = wid & 1;        // 2 warps in M (64 rows each)
    const int warpN = wid >> 1;       // 2 warps in N (64 cols each)
    const int m0 = blockIdx.y * MT;
    const int n0 = blockIdx.x * NT;

    // cp.async: 1024 16B-chunks per stage, 8 per thread (swizzled dst)
    uint32_t sOff[8];
#pragma unroll
    for (int i = 0; i < 8; ++i) {
        int c   = tid + i * 128;       // 0..1023
        int row = c >> 2;              // 0..255
        uint32_t off = (uint32_t)row * ROW_BYTES + (c & 3) * 16;
        sOff[i] = SWZ(off);
    }

    // ldmatrix base offsets (kk=0); kk=1 -> XOR 32
    uint32_t aOff[4], bOff[4];
#pragma unroll
    for (int mi = 0; mi < 4; ++mi) {
        int r = warpM * 64 + mi * 16 + (lane & 15);
        uint32_t off = (uint32_t)r * ROW_BYTES + (lane >> 4) * 16;
        aOff[mi] = SWZ(off);
    }
#pragma unroll
    for (int nh = 0; nh < 4; ++nh) {
        int r = 128 + warpN * 64 + nh * 16 + ((lane >> 4) & 1) * 8 + (lane & 7);
        uint32_t off = (uint32_t)r * ROW_BYTES + ((lane >> 3) & 1) * 16;
        bOff[nh] = SWZ(off);
    }

    float acc[4][8][4];
#pragma unroll
    for (int mi = 0; mi < 4; ++mi)
#pragma unroll
        for (int ni = 0; ni < 8; ++ni)
#pragma unroll
            for (int e = 0; e < 4; ++e) acc[mi][ni][e] = 0.f;

    auto issue_load = [&](int j, int slot) {
        const int k0 = j * KC;
        const uint32_t stBase = sb + slot * STAGE_BYTES;
#pragma unroll
        for (int i = 0; i < 8; ++i) {
            int c   = tid + i * 128;
            int row = c >> 2;
            int off = (c & 3) * 8;     // halves within row
            const __half* g;
            if (i < 4) g = A + (size_t)(m0 + row)       * K + k0 + off;
            else       g = B + (size_t)(n0 + row - 128) * K + k0 + off;
            CP_ASYNC_16(stBase + sOff[i], g);
        }
        CP_COMMIT();
    };

    issue_load(0, 0);
    issue_load(1, 1);
    issue_load(2, 2);
    issue_load(3, 3);

    int slot = 0;
    for (int j = 0; j < NIT; ++j) {
        CP_WAITN(3);                   // load j landed; up to 3 still flying
        __syncthreads();
        const int jn = j + 4;
        if (jn < NIT) {
            int sl = slot + 4; if (sl >= STAGES) sl -= STAGES;
            issue_load(jn, sl);
        } else {
            CP_COMMIT();               // keep group counting aligned
        }

        const uint32_t stBase = sb + slot * STAGE_BYTES;

#pragma unroll
        for (int kk = 0; kk < 2; ++kk) {
            const uint32_t kx = kk * 32;
            uint32_t bf[8][2];
#pragma unroll
            for (int nh = 0; nh < 4; ++nh) {
                uint32_t r0, r1, r2, r3;
                LDMATRIX_X4(r0, r1, r2, r3, stBase + (bOff[nh] ^ kx));
                bf[2*nh][0] = r0;   bf[2*nh][1] = r1;
                bf[2*nh+1][0] = r2; bf[2*nh+1][1] = r3;
            }
            uint32_t a[4][4];
#pragma unroll
            for (int mi = 0; mi < 4; ++mi)
                LDMATRIX_X4(a[mi][0], a[mi][1], a[mi][2], a[mi][3],
                            stBase + (aOff[mi] ^ kx));
#pragma unroll
            for (int mi = 0; mi < 4; ++mi)
#pragma unroll
                for (int ni = 0; ni < 8; ++ni)
                    MMA_F16(acc[mi][ni], a[mi][0], a[mi][1], a[mi][2], a[mi][3],
                            bf[ni][0], bf[ni][1]);
        }
        if (++slot >= STAGES) slot = 0;
    }

    // ------------------------------------------------------------ epilogue
    const int gid = lane >> 2;
    const int tig = lane & 3;

#pragma unroll
    for (int mi = 0; mi < 4; ++mi) {
        int rbase = m0 + warpM * 64 + mi * 16 + gid;
#pragma unroll
        for (int half = 0; half < 2; ++half) {
            int m = rbase + half * 8;
            float sc = (MODE == 1) ? g_scale[m] : 0.f;
#pragma unroll
            for (int ni = 0; ni < 8; ++ni) {
                int n = n0 + warpN * 64 + ni * 8 + tig * 2;
                float v0 = acc[mi][ni][half * 2 + 0];
                float v1 = acc[mi][ni][half * 2 + 1];
                if (MODE == 0) {
                    if (n0 < DINNER) {
                        *(__half2*)&g_xi[(size_t)m * DINNER + n] =
                            __halves2half2(__float2half(v0), __float2half(v1));
                    } else {
                        float s0 = sigmoidf_(v0), s1 = sigmoidf_(v1);
                        size_t idx = (size_t)m * DINNER + (n - DINNER);
                        *(__half2*)&g_gate[idx] =
                            __halves2half2(__float2half(s0), __float2half(s1));
                    }
                } else {
                    *(float2*)&out[(size_t)m * DMODEL + n] = make_float2(sc * v0, sc * v1);
                }
            }
        }
    }
}

// ---------------------------------------------------------------- conv + dt (fp16 xi)
__global__ void __launch_bounds__(256) conv_dt_kernel(const float* __restrict__ conv_w,
                                                      const float* __restrict__ conv_b,
                                                      const float* __restrict__ W_dt,
                                                      const float* __restrict__ b_dt) {
    const int warp = threadIdx.x >> 5;
    const int lane = threadIdx.x & 31;
    const int m = blockIdx.x * 8 + warp;
    const int s = m & (SEQ - 1);

    float acc[16];
#pragma unroll
    for (int i = 0; i < 16; ++i) acc[i] = 0.f;

    const __half* xi_row = g_xi + (size_t)m * DINNER;

    for (int it = 0; it < DINNER / 128; ++it) {
        int e = it * 128 + lane * 4;
        float4 w0 = *(const float4*)(conv_w + (size_t)(e + 0) * 4);
        float4 w1 = *(const float4*)(conv_w + (size_t)(e + 1) * 4);
        float4 w2 = *(const float4*)(conv_w + (size_t)(e + 2) * 4);
        float4 w3 = *(const float4*)(conv_w + (size_t)(e + 3) * 4);
        float4 cb = *(const float4*)(conv_b + e);

        float4 xk[4];
#pragma unroll
        for (int k = 0; k < 4; ++k) {
            int d = 3 - k;
            if (s - d >= 0) {
                const __half2* p = (const __half2*)(xi_row - (size_t)d * DINNER + e);
                float2 lo = __half22float2(p[0]);
                float2 hi = __half22float2(p[1]);
                xk[k] = make_float4(lo.x, lo.y, hi.x, hi.y);
            } else {
                xk[k] = make_float4(0.f, 0.f, 0.f, 0.f);
            }
        }
        float4 v;
        v.x = fmaf(w0.x, xk[0].x, fmaf(w0.y, xk[1].x, fmaf(w0.z, xk[2].x, fmaf(w0.w, xk[3].x, cb.x))));
        v.y = fmaf(w1.x, xk[0].y, fmaf(w1.y, xk[1].y, fmaf(w1.z, xk[2].y, fmaf(w1.w, xk[3].y, cb.y))));
        v.z = fmaf(w2.x, xk[0].z, fmaf(w2.y, xk[1].z, fmaf(w2.z, xk[2].z, fmaf(w2.w, xk[3].z, cb.z))));
        v.w = fmaf(w3.x, xk[0].w, fmaf(w3.y, xk[1].w, fmaf(w3.z, xk[2].w, fmaf(w3.w, xk[3].w, cb.w))));

        float4 xs;
        xs.x = v.x * sigmoidf_(v.x);
        xs.y = v.y * sigmoidf_(v.y);
        xs.z = v.z * sigmoidf_(v.z);
        xs.w = v.w * sigmoidf_(v.w);

        if (it == 0 && lane < 4) {
            g_u[m * DSTATE + e + 0] = xs.x;
            g_u[m * DSTATE + e + 1] = xs.y;
            g_u[m * DSTATE + e + 2] = xs.z;
            g_u[m * DSTATE + e + 3] = xs.w;
        }
#pragma unroll
        for (int i = 0; i < 16; ++i) {
            float4 wd = *(const float4*)(W_dt + (size_t)i * DINNER + e);
            acc[i] = fmaf(xs.x, wd.x, acc[i]);
            acc[i] = fmaf(xs.y, wd.y, acc[i]);
            acc[i] = fmaf(xs.z, wd.z, acc[i]);
            acc[i] = fmaf(xs.w, wd.w, acc[i]);
        }
    }
#pragma unroll
    for (int i = 0; i < 16; ++i) {
#pragma unroll
        for (int off = 16; off > 0; off >>= 1)
            acc[i] += __shfl_xor_sync(0xffffffffu, acc[i], off);
    }
    if (lane == 0) {
#pragma unroll
        for (int i = 0; i < 16; ++i) {
            float z = acc[i] + b_dt[i];
            float sp = (z > 20.f) ? z : log1pf(expf(z));
            g_a[m * DSTATE + i] = 1.0f + sp;
        }
    }
}

// ---------------------------------------------------------------- scan
__global__ void __launch_bounds__(512) scan_kernel(const float* __restrict__ A_log) {
    const int b = blockIdx.x;
    const int tid = threadIdx.x;
    const int chunk = tid >> 4;
    const int j = tid & 15;
    const int t0 = chunk * 64;

    __shared__ float sP[32][16];
    __shared__ float sQ[32][16];
    __shared__ float sH[32][16];

    const float* a = g_a + (size_t)b * SEQ * DSTATE;
    const float* u = g_u + (size_t)b * SEQ * DSTATE;

    float P = 1.f, q = 0.f;
    for (int i = 0; i < 64; ++i) {
        float av = a[(t0 + i) * DSTATE + j];
        float uv = u[(t0 + i) * DSTATE + j];
        q = fmaf(q, av, uv);
        P *= av;
    }
    sP[chunk][j] = P;
    sQ[chunk][j] = q;
    __syncthreads();

    if (tid < 16) {
        float h = 0.f;
        for (int k = 0; k < 32; ++k) {
            sH[k][tid] = h;
            h = fmaf(sP[k][tid], h, sQ[k][tid]);
        }
    }
    __syncthreads();

    const float Aj = -expf(A_log[j]);
    float h = sH[chunk][j];
    for (int i = 0; i < 64; ++i) {
        int t = t0 + i;
        float av = a[t * DSTATE + j];
        float uv = u[t * DSTATE + j];
        h = fmaf(h, av, uv);
        float c = Aj * h;
        c += __shfl_xor_sync(0xffffffffu, c, 8, 16);
        c += __shfl_xor_sync(0xffffffffu, c, 4, 16);
        c += __shfl_xor_sync(0xffffffffu, c, 2, 16);
        c += __shfl_xor_sync(0xffffffffu, c, 1, 16);
        if (j == 0) g_scale[b * SEQ + t] = c * (float)DINNER;
    }
}

// ---------------------------------------------------------------- host
extern "C" void kernel_launch(void* const* d_in, const int* in_sizes, int n_in,
                              void* d_out, int out_size) {
    const float* x      = (const float*)d_in[0];
    const float* W_in   = (const float*)d_in[1];
    const float* conv_w = (const float*)d_in[2];
    const float* conv_b = (const float*)d_in[3];
    const float* W_dt   = (const float*)d_in[4];
    const float* b_dt   = (const float*)d_in[5];
    const float* A_log  = (const float*)d_in[6];
    const float* W_out  = (const float*)d_in[7];
    float* out = (float*)d_out;
    (void)in_sizes; (void)n_in; (void)out_size;

    void *px, *pwi, *pwo, *pg;
    cudaGetSymbolAddress(&px, g_x);
    cudaGetSymbolAddress(&pwi, g_win);
    cudaGetSymbolAddress(&pwo, g_wout);
    cudaGetSymbolAddress(&pg, g_gate);

    cudaFuncSetAttribute(gemm_mma<0, DMODEL>, cudaFuncAttributeMaxDynamicSharedMemorySize, SMEM_BYTES);
    cudaFuncSetAttribute(gemm_mma<1, DINNER>, cudaFuncAttributeMaxDynamicSharedMemorySize, SMEM_BYTES);

    // preprocessing: fp32 -> fp16 conversions
    cvt_f16<<<(M_TOT * DMODEL / 4 + 255) / 256, 256>>>(x, (__half*)px, M_TOT * DMODEL / 4);
    cvt_f16<<<(2 * DINNER * DMODEL / 4 + 255) / 256, 256>>>(W_in, (__half*)pwi, 2 * DINNER * DMODEL / 4);
    cvt_f16<<<(DMODEL * DINNER / 4 + 255) / 256, 256>>>(W_out, (__half*)pwo, DMODEL * DINNER / 4);

    // GEMM1: xz = x @ W_in^T  (M=4096, N=8192, K=2048)
    gemm_mma<0, DMODEL><<<dim3(2 * DINNER / NT, M_TOT / MT), 128, SMEM_BYTES>>>(
        (const __half*)px, (const __half*)pwi, nullptr);

    // conv + silu + dt
    conv_dt_kernel<<<M_TOT / 8, 256>>>(conv_w, conv_b, W_dt, b_dt);
    // selective scan
    scan_kernel<<<BATCH, 512>>>(A_log);

    // GEMM2: out = scale * (sigmoid(gate) @ W_out^T)  (M=4096, N=2048, K=4096)
    gemm_mma<1, DINNER><<<dim3(DMODEL / NT, M_TOT / MT), 128, SMEM_BYTES>>>(
        (const __half*)pg, (const __half*)pwo, out);
}

// round 15
// speedup vs baseline: 1.0064x; 1.0032x over previous
#include <cuda_runtime.h>
#include <cuda_fp16.h>
#include <math.h>
#include <cstdint>

// ---------------------------------------------------------------- constants
#define BATCH 2
#define SEQ 2048
#define DMODEL 2048
#define DINNER 4096
#define DSTATE 16
#define M_TOT (BATCH*SEQ)          // 4096

// GEMM tiling: 128x128 CTA, 128 thr (4 warps x 64x64), KC=32, 5 stages
#define MT 128
#define NT 128
#define KC 32
#define STAGES 5
#define ROW_BYTES 64                               // 32 halves, swizzled
#define STAGE_ROWS 256                             // A (128) + B (128)
#define STAGE_BYTES (STAGE_ROWS * ROW_BYTES)       // 16384
#define SMEM_BYTES (STAGES * STAGE_BYTES)          // 81920

// swizzle: chunk(16B, bits[4:5]) ^= (row>>1)&3  (row stride 64B)
#define SWZ(off) ((off) ^ (((off) >> 3) & 0x30))

// ---------------------------------------------------------------- scratch
__device__ __align__(1024) __half g_xi[(size_t)M_TOT * DINNER];
__device__ __align__(1024) __half g_x[(size_t)M_TOT * DMODEL];
__device__ __align__(1024) __half g_win[(size_t)2*DINNER * DMODEL];
__device__ __align__(1024) __half g_wout[(size_t)DMODEL * DINNER];
__device__ __align__(1024) __half g_gate[(size_t)M_TOT * DINNER];
__device__ float g_a[M_TOT * DSTATE];
__device__ float g_u[M_TOT * DSTATE];
__device__ float g_scale[M_TOT];

static __device__ __forceinline__ float sigmoidf_(float v) {
    return 1.0f / (1.0f + expf(-v));
}

__device__ __forceinline__ uint32_t smem_u32(const void* p) {
    uint32_t a;
    asm("{ .reg .u64 t; cvta.to.shared.u64 t, %1; cvt.u32.u64 %0, t; }" : "=r"(a) : "l"(p));
    return a;
}

#define CP_ASYNC_16(saddr, gptr) \
    asm volatile("cp.async.cg.shared.global [%0], [%1], 16;" :: "r"(saddr), "l"(gptr))
#define CP_COMMIT() asm volatile("cp.async.commit_group;" ::: "memory")
#define CP_WAITN(n) asm volatile("cp.async.wait_group %0;" :: "n"(n) : "memory")

#define LDMATRIX_X4(r0,r1,r2,r3, addr) \
    asm volatile("ldmatrix.sync.aligned.m8n8.x4.shared.b16 {%0,%1,%2,%3}, [%4];" \
                 : "=r"(r0), "=r"(r1), "=r"(r2), "=r"(r3) : "r"(addr))

#define MMA_F16(c, a0,a1,a2,a3, b0,b1) \
    asm volatile("mma.sync.aligned.m16n8k16.row.col.f32.f16.f16.f32 " \
                 "{%0,%1,%2,%3}, {%4,%5,%6,%7}, {%8,%9}, {%0,%1,%2,%3};" \
                 : "+f"((c)[0]), "+f"((c)[1]), "+f"((c)[2]), "+f"((c)[3]) \
                 : "r"(a0), "r"(a1), "r"(a2), "r"(a3), "r"(b0), "r"(b1))

// ---------------------------------------------------------------- preprocessing
__global__ void __launch_bounds__(256) cvt_f16(const float* __restrict__ in,
                                               __half* __restrict__ o,
                                               int n4) {
    int i = blockIdx.x * 256 + threadIdx.x;
    if (i >= n4) return;
    float4 v = ((const float4*)in)[i];
    ((__half2*)o)[2*i]   = __halves2half2(__float2half(v.x), __float2half(v.y));
    ((__half2*)o)[2*i+1] = __halves2half2(__float2half(v.z), __float2half(v.w));
}

// ---------------------------------------------------------------- mma GEMM
// 128 threads, 4 warps x (64x64 warp tile), 128x128 CTA tile, 2 CTAs/SM.
// Stage-level fragment prefetch: all 16 LDSM of the stage, then 64 MMAs.
// MODE 0: n<4096 -> g_xi fp16 ; n>=4096 -> sigmoid -> g_gate fp16
// MODE 1: out[m,n] = g_scale[m]*acc
template <int MODE, int K>
__global__ void __launch_bounds__(128, 2) gemm_mma(const __half* __restrict__ A,
                                                   const __half* __restrict__ B,
                                                   float* __restrict__ out) {
    constexpr int NIT = K / KC;

    extern __shared__ char smem[];
    const uint32_t sb = smem_u32(smem);

    const int tid  = threadIdx.x;
    const int lane = tid & 31;
    const int wid  = tid >> 5;        // 0..3
    const int warpM = wid & 1;        // 2 warps in M (64 rows each)
    const int warpN = wid >> 1;       // 2 warps in N (64 cols each)
    const int m0 = blockIdx.y * MT;
    const int n0 = blockIdx.x * NT;

    // cp.async: 1024 16B-chunks per stage, 8 per thread (swizzled dst)
    uint32_t sOff[8];
#pragma unroll
    for (int i = 0; i < 8; ++i) {
        int c   = tid + i * 128;       // 0..1023
        int row = c >> 2;              // 0..255
        uint32_t off = (uint32_t)row * ROW_BYTES + (c & 3) * 16;
        sOff[i] = SWZ(off);
    }

    // ldmatrix base offsets (kk=0); kk=1 -> XOR 32
    uint32_t aOff[4], bOff[4];
#pragma unroll
    for (int mi = 0; mi < 4; ++mi) {
        int r = warpM * 64 + mi * 16 + (lane & 15);
        uint32_t off = (uint32_t)r * ROW_BYTES + (lane >> 4) * 16;
        aOff[mi] = SWZ(off);
    }
#pragma unroll
    for (int nh = 0; nh < 4; ++nh) {
        int r = 128 + warpN * 64 + nh * 16 + ((lane >> 4) & 1) * 8 + (lane & 7);
        uint32_t off = (uint32_t)r * ROW_BYTES + ((lane >> 3) & 1) * 16;
        bOff[nh] = SWZ(off);
    }

    float acc[4][8][4];
#pragma unroll
    for (int mi = 0; mi < 4; ++mi)
#pragma unroll
        for (int ni = 0; ni < 8; ++ni)
#pragma unroll
            for (int e = 0; e < 4; ++e) acc[mi][ni][e] = 0.f;

    auto issue_load = [&](int j, int slot) {
        const int k0 = j * KC;
        const uint32_t stBase = sb + slot * STAGE_BYTES;
#pragma unroll
        for (int i = 0; i < 8; ++i) {
            int c   = tid + i * 128;
            int row = c >> 2;
            int off = (c & 3) * 8;     // halves within row
            const __half* g;
            if (i < 4) g = A + (size_t)(m0 + row)       * K + k0 + off;
            else       g = B + (size_t)(n0 + row - 128) * K + k0 + off;
            CP_ASYNC_16(stBase + sOff[i], g);
        }
        CP_COMMIT();
    };

    issue_load(0, 0);
    issue_load(1, 1);
    issue_load(2, 2);
    issue_load(3, 3);

    int slot = 0;
    for (int j = 0; j < NIT; ++j) {
        CP_WAITN(3);                   // load j landed; up to 3 still flying
        __syncthreads();
        const int jn = j + 4;
        if (jn < NIT) {
            int sl = slot + 4; if (sl >= STAGES) sl -= STAGES;
            issue_load(jn, sl);
        } else {
            CP_COMMIT();               // keep group counting aligned
        }

        const uint32_t stBase = sb + slot * STAGE_BYTES;

        // ---- load ALL fragments of this stage first (16 LDSM) ----
        uint32_t a[2][4][4];
        uint32_t bf[2][8][2];
#pragma unroll
        for (int kk = 0; kk < 2; ++kk) {
            const uint32_t kx = kk * 32;
#pragma unroll
            for (int nh = 0; nh < 4; ++nh) {
                uint32_t r0, r1, r2, r3;
                LDMATRIX_X4(r0, r1, r2, r3, stBase + (bOff[nh] ^ kx));
                bf[kk][2*nh][0] = r0;   bf[kk][2*nh][1] = r1;
                bf[kk][2*nh+1][0] = r2; bf[kk][2*nh+1][1] = r3;
            }
#pragma unroll
            for (int mi = 0; mi < 4; ++mi)
                LDMATRIX_X4(a[kk][mi][0], a[kk][mi][1], a[kk][mi][2], a[kk][mi][3],
                            stBase + (aOff[mi] ^ kx));
        }
        // ---- then issue all 64 MMAs ----
#pragma unroll
        for (int kk = 0; kk < 2; ++kk)
#pragma unroll
            for (int mi = 0; mi < 4; ++mi)
#pragma unroll
                for (int ni = 0; ni < 8; ++ni)
                    MMA_F16(acc[mi][ni],
                            a[kk][mi][0], a[kk][mi][1], a[kk][mi][2], a[kk][mi][3],
                            bf[kk][ni][0], bf[kk][ni][1]);

        if (++slot >= STAGES) slot = 0;
    }

    // ------------------------------------------------------------ epilogue
    const int gid = lane >> 2;
    const int tig = lane & 3;

#pragma unroll
    for (int mi = 0; mi < 4; ++mi) {
        int rbase = m0 + warpM * 64 + mi * 16 + gid;
#pragma unroll
        for (int half = 0; half < 2; ++half) {
            int m = rbase + half * 8;
            float sc = (MODE == 1) ? g_scale[m] : 0.f;
#pragma unroll
            for (int ni = 0; ni < 8; ++ni) {
                int n = n0 + warpN * 64 + ni * 8 + tig * 2;
                float v0 = acc[mi][ni][half * 2 + 0];
                float v1 = acc[mi][ni][half * 2 + 1];
                if (MODE == 0) {
                    if (n0 < DINNER) {
                        *(__half2*)&g_xi[(size_t)m * DINNER + n] =
                            __halves2half2(__float2half(v0), __float2half(v1));
                    } else {
                        float s0 = sigmoidf_(v0), s1 = sigmoidf_(v1);
                        size_t idx = (size_t)m * DINNER + (n - DINNER);
                        *(__half2*)&g_gate[idx] =
                            __halves2half2(__float2half(s0), __float2half(s1));
                    }
                } else {
                    *(float2*)&out[(size_t)m * DMODEL + n] = make_float2(sc * v0, sc * v1);
                }
            }
        }
    }
}

// ---------------------------------------------------------------- conv + dt (fp16 xi)
__global__ void __launch_bounds__(256) conv_dt_kernel(const float* __restrict__ conv_w,
                                                      const float* __restrict__ conv_b,
                                                      const float* __restrict__ W_dt,
                                                      const float* __restrict__ b_dt) {
    const int warp = threadIdx.x >> 5;
    const int lane = threadIdx.x & 31;
    const int m = blockIdx.x * 8 + warp;
    const int s = m & (SEQ - 1);

    float acc[16];
#pragma unroll
    for (int i = 0; i < 16; ++i) acc[i] = 0.f;

    const __half* xi_row = g_xi + (size_t)m * DINNER;

    for (int it = 0; it < DINNER / 128; ++it) {
        int e = it * 128 + lane * 4;
        float4 w0 = *(const float4*)(conv_w + (size_t)(e + 0) * 4);
        float4 w1 = *(const float4*)(conv_w + (size_t)(e + 1) * 4);
        float4 w2 = *(const float4*)(conv_w + (size_t)(e + 2) * 4);
        float4 w3 = *(const float4*)(conv_w + (size_t)(e + 3) * 4);
        float4 cb = *(const float4*)(conv_b + e);

        float4 xk[4];
#pragma unroll
        for (int k = 0; k < 4; ++k) {
            int d = 3 - k;
            if (s - d >= 0) {
                const __half2* p = (const __half2*)(xi_row - (size_t)d * DINNER + e);
                float2 lo = __half22float2(p[0]);
                float2 hi = __half22float2(p[1]);
                xk[k] = make_float4(lo.x, lo.y, hi.x, hi.y);
            } else {
                xk[k] = make_float4(0.f, 0.f, 0.f, 0.f);
            }
        }
        float4 v;
        v.x = fmaf(w0.x, xk[0].x, fmaf(w0.y, xk[1].x, fmaf(w0.z, xk[2].x, fmaf(w0.w, xk[3].x, cb.x))));
        v.y = fmaf(w1.x, xk[0].y, fmaf(w1.y, xk[1].y, fmaf(w1.z, xk[2].y, fmaf(w1.w, xk[3].y, cb.y))));
        v.z = fmaf(w2.x, xk[0].z, fmaf(w2.y, xk[1].z, fmaf(w2.z, xk[2].z, fmaf(w2.w, xk[3].z, cb.z))));
        v.w = fmaf(w3.x, xk[0].w, fmaf(w3.y, xk[1].w, fmaf(w3.z, xk[2].w, fmaf(w3.w, xk[3].w, cb.w))));

        float4 xs;
        xs.x = v.x * sigmoidf_(v.x);
        xs.y = v.y * sigmoidf_(v.y);
        xs.z = v.z * sigmoidf_(v.z);
        xs.w = v.w * sigmoidf_(v.w);

        if (it == 0 && lane < 4) {
            g_u[m * DSTATE + e + 0] = xs.x;
            g_u[m * DSTATE + e + 1] = xs.y;
            g_u[m * DSTATE + e + 2] = xs.z;
            g_u[m * DSTATE + e + 3] = xs.w;
        }
#pragma unroll
        for (int i = 0; i < 16; ++i) {
            float4 wd = *(const float4*)(W_dt + (size_t)i * DINNER + e);
            acc[i] = fmaf(xs.x, wd.x, acc[i]);
            acc[i] = fmaf(xs.y, wd.y, acc[i]);
            acc[i] = fmaf(xs.z, wd.z, acc[i]);
            acc[i] = fmaf(xs.w, wd.w, acc[i]);
        }
    }
#pragma unroll
    for (int i = 0; i < 16; ++i) {
#pragma unroll
        for (int off = 16; off > 0; off >>= 1)
            acc[i] += __shfl_xor_sync(0xffffffffu, acc[i], off);
    }
    if (lane == 0) {
#pragma unroll
        for (int i = 0; i < 16; ++i) {
            float z = acc[i] + b_dt[i];
            float sp = (z > 20.f) ? z : log1pf(expf(z));
            g_a[m * DSTATE + i] = 1.0f + sp;
        }
    }
}

// ---------------------------------------------------------------- scan
__global__ void __launch_bounds__(512) scan_kernel(const float* __restrict__ A_log) {
    const int b = blockIdx.x;
    const int tid = threadIdx.x;
    const int chunk = tid >> 4;
    const int j = tid & 15;
    const int t0 = chunk * 64;

    __shared__ float sP[32][16];
    __shared__ float sQ[32][16];
    __shared__ float sH[32][16];

    const float* a = g_a + (size_t)b * SEQ * DSTATE;
    const float* u = g_u + (size_t)b * SEQ * DSTATE;

    float P = 1.f, q = 0.f;
    for (int i = 0; i < 64; ++i) {
        float av = a[(t0 + i) * DSTATE + j];
        float uv = u[(t0 + i) * DSTATE + j];
        q = fmaf(q, av, uv);
        P *= av;
    }
    sP[chunk][j] = P;
    sQ[chunk][j] = q;
    __syncthreads();

    if (tid < 16) {
        float h = 0.f;
        for (int k = 0; k < 32; ++k) {
            sH[k][tid] = h;
            h = fmaf(sP[k][tid], h, sQ[k][tid]);
        }
    }
    __syncthreads();

    const float Aj = -expf(A_log[j]);
    float h = sH[chunk][j];
    for (int i = 0; i < 64; ++i) {
        int t = t0 + i;
        float av = a[t * DSTATE + j];
        float uv = u[t * DSTATE + j];
        h = fmaf(h, av, uv);
        float c = Aj * h;
        c += __shfl_xor_sync(0xffffffffu, c, 8, 16);
        c += __shfl_xor_sync(0xffffffffu, c, 4, 16);
        c += __shfl_xor_sync(0xffffffffu, c, 2, 16);
        c += __shfl_xor_sync(0xffffffffu, c, 1, 16);
        if (j == 0) g_scale[b * SEQ + t] = c * (float)DINNER;
    }
}

// ---------------------------------------------------------------- host
extern "C" void kernel_launch(void* const* d_in, const int* in_sizes, int n_in,
                              void* d_out, int out_size) {
    const float* x      = (const float*)d_in[0];
    const float* W_in   = (const float*)d_in[1];
    const float* conv_w = (const float*)d_in[2];
    const float* conv_b = (const float*)d_in[3];
    const float* W_dt   = (const float*)d_in[4];
    const float* b_dt   = (const float*)d_in[5];
    const float* A_log  = (const float*)d_in[6];
    const float* W_out  = (const float*)d_in[7];
    float* out = (float*)d_out;
    (void)in_sizes; (void)n_in; (void)out_size;

    void *px, *pwi, *pwo, *pg;
    cudaGetSymbolAddress(&px, g_x);
    cudaGetSymbolAddress(&pwi, g_win);
    cudaGetSymbolAddress(&pwo, g_wout);
    cudaGetSymbolAddress(&pg, g_gate);

    cudaFuncSetAttribute(gemm_mma<0, DMODEL>, cudaFuncAttributeMaxDynamicSharedMemorySize, SMEM_BYTES);
    cudaFuncSetAttribute(gemm_mma<1, DINNER>, cudaFuncAttributeMaxDynamicSharedMemorySize, SMEM_BYTES);

    // preprocessing: fp32 -> fp16 conversions
    cvt_f16<<<(M_TOT * DMODEL / 4 + 255) / 256, 256>>>(x, (__half*)px, M_TOT * DMODEL / 4);
    cvt_f16<<<(2 * DINNER * DMODEL / 4 + 255) / 256, 256>>>(W_in, (__half*)pwi, 2 * DINNER * DMODEL / 4);
    cvt_f16<<<(DMODEL * DINNER / 4 + 255) / 256, 256>>>(W_out, (__half*)pwo, DMODEL * DINNER / 4);

    // GEMM1: xz = x @ W_in^T  (M=4096, N=8192, K=2048)
    gemm_mma<0, DMODEL><<<dim3(2 * DINNER / NT, M_TOT / MT), 128, SMEM_BYTES>>>(
        (const __half*)px, (const __half*)pwi, nullptr);

    // conv + silu + dt
    conv_dt_kernel<<<M_TOT / 8, 256>>>(conv_w, conv_b, W_dt, b_dt);
    // selective scan
    scan_kernel<<<BATCH, 512>>>(A_log);

    // GEMM2: out = scale * (sigmoid(gate) @ W_out^T)  (M=4096, N=2048, K=4096)
    gemm_mma<1, DINNER><<<dim3(DMODEL / NT, M_TOT / MT), 128, SMEM_BYTES>>>(
        (const __half*)pg, (const __half*)pwo, out);
}

// round 16
// speedup vs baseline: 1.0605x; 1.0537x over previous
#include <cuda_runtime.h>
#include <cuda_fp16.h>
#include <math.h>
#include <cstdint>

// ---------------------------------------------------------------- constants
#define BATCH 2
#define SEQ 2048
#define DMODEL 2048
#define DINNER 4096
#define DSTATE 16
#define M_TOT (BATCH*SEQ)          // 4096

// GEMM tiling (champion): 128x128 CTA, 128 thr (4 warps x 64x64), KC=32, 5 stages
#define MT 128
#define NT 128
#define KC 32
#define STAGES 5
#define ROW_BYTES 64                               // 32 halves, swizzled
#define STAGE_ROWS 256                             // A (128) + B (128)
#define STAGE_BYTES (STAGE_ROWS * ROW_BYTES)       // 16384
#define SMEM_BYTES (STAGES * STAGE_BYTES)          // 81920

// swizzle: chunk(16B, bits[4:5]) ^= (row>>1)&3  (row stride 64B)
#define SWZ(off) ((off) ^ (((off) >> 3) & 0x30))

// ---------------------------------------------------------------- scratch
__device__ __align__(1024) __half g_xi[(size_t)M_TOT * DINNER];
__device__ __align__(1024) __half g_x[(size_t)M_TOT * DMODEL];
__device__ __align__(1024) __half g_win[(size_t)2*DINNER * DMODEL];
__device__ __align__(1024) __half g_wout[(size_t)DMODEL * DINNER];
__device__ __align__(1024) __half g_gate[(size_t)M_TOT * DINNER];
__device__ float g_a[M_TOT * DSTATE];
__device__ float g_u[M_TOT * DSTATE];
__device__ float g_scale[M_TOT];

static __device__ __forceinline__ float sigmoidf_(float v) {
    return 1.0f / (1.0f + expf(-v));
}

__device__ __forceinline__ uint32_t smem_u32(const void* p) {
    uint32_t a;
    asm("{ .reg .u64 t; cvta.to.shared.u64 t, %1; cvt.u32.u64 %0, t; }" : "=r"(a) : "l"(p));
    return a;
}

#define CP_ASYNC_16(saddr, gptr) \
    asm volatile("cp.async.cg.shared.global [%0], [%1], 16;" :: "r"(saddr), "l"(gptr))
#define CP_COMMIT() asm volatile("cp.async.commit_group;" ::: "memory")
#define CP_WAITN(n) asm volatile("cp.async.wait_group %0;" :: "n"(n) : "memory")

#define LDMATRIX_X4(r0,r1,r2,r3, addr) \
    asm volatile("ldmatrix.sync.aligned.m8n8.x4.shared.b16 {%0,%1,%2,%3}, [%4];" \
                 : "=r"(r0), "=r"(r1), "=r"(r2), "=r"(r3) : "r"(addr))

#define MMA_F16(c, a0,a1,a2,a3, b0,b1) \
    asm volatile("mma.sync.aligned.m16n8k16.row.col.f32.f16.f16.f32 " \
                 "{%0,%1,%2,%3}, {%4,%5,%6,%7}, {%8,%9}, {%0,%1,%2,%3};" \
                 : "+f"((c)[0]), "+f"((c)[1]), "+f"((c)[2]), "+f"((c)[3]) \
                 : "r"(a0), "r"(a1), "r"(a2), "r"(a3), "r"(b0), "r"(b1))

// ---------------------------------------------------------------- preprocessing
__global__ void __launch_bounds__(256) cvt_f16(const float* __restrict__ in,
                                               __half* __restrict__ o,
                                               int n4) {
    int i = blockIdx.x * 256 + threadIdx.x;
    if (i >= n4) return;
    float4 v = ((const float4*)in)[i];
    ((__half2*)o)[2*i]   = __halves2half2(__float2half(v.x), __float2half(v.y));
    ((__half2*)o)[2*i+1] = __halves2half2(__float2half(v.z), __float2half(v.w));
}

// ---------------------------------------------------------------- mma GEMM
// 128 threads, 4 warps x (64x64 warp tile), 128x128 CTA tile, 2 CTAs/SM.
// MODE 0: writes g_xi fp16 (xi half)
// MODE 2: sigmoid -> g_gate fp16 (gate half; B pre-offset by caller)
// MODE 1: out[m,n] = g_scale[m]*acc
template <int MODE, int K>
__global__ void __launch_bounds__(128, 2) gemm_mma(const __half* __restrict__ A,
                                                   const __half* __restrict__ B,
                                                   float* __restrict__ out) {
    constexpr int NIT = K / KC;

    extern __shared__ char smem[];
    const uint32_t sb = smem_u32(smem);

    const int tid  = threadIdx.x;
    const int lane = tid & 31;
    const int wid  = tid >> 5;        // 0..3
    const int warpM = wid & 1;        // 2 warps in M (64 rows each)
    const int warpN = wid >> 1;       // 2 warps in N (64 cols each)
    const int m0 = blockIdx.y * MT;
    const int n0 = blockIdx.x * NT;

    // cp.async: 1024 16B-chunks per stage, 8 per thread (swizzled dst)
    uint32_t sOff[8];
#pragma unroll
    for (int i = 0; i < 8; ++i) {
        int c   = tid + i * 128;       // 0..1023
        int row = c >> 2;              // 0..255
        uint32_t off = (uint32_t)row * ROW_BYTES + (c & 3) * 16;
        sOff[i] = SWZ(off);
    }

    // ldmatrix base offsets (kk=0); kk=1 -> XOR 32
    uint32_t aOff[4], bOff[4];
#pragma unroll
    for (int mi = 0; mi < 4; ++mi) {
        int r = warpM * 64 + mi * 16 + (lane & 15);
        uint32_t off = (uint32_t)r * ROW_BYTES + (lane >> 4) * 16;
        aOff[mi] = SWZ(off);
    }
#pragma unroll
    for (int nh = 0; nh < 4; ++nh) {
        int r = 128 + warpN * 64 + nh * 16 + ((lane >> 4) & 1) * 8 + (lane & 7);
        uint32_t off = (uint32_t)r * ROW_BYTES + ((lane >> 3) & 1) * 16;
        bOff[nh] = SWZ(off);
    }

    float acc[4][8][4];
#pragma unroll
    for (int mi = 0; mi < 4; ++mi)
#pragma unroll
        for (int ni = 0; ni < 8; ++ni)
#pragma unroll
            for (int e = 0; e < 4; ++e) acc[mi][ni][e] = 0.f;

    auto issue_load = [&](int j, int slot) {
        const int k0 = j * KC;
        const uint32_t stBase = sb + slot * STAGE_BYTES;
#pragma unroll
        for (int i = 0; i < 8; ++i) {
            int c   = tid + i * 128;
            int row = c >> 2;
            int off = (c & 3) * 8;     // halves within row
            const __half* g;
            if (i < 4) g = A + (size_t)(m0 + row)       * K + k0 + off;
            else       g = B + (size_t)(n0 + row - 128) * K + k0 + off;
            CP_ASYNC_16(stBase + sOff[i], g);
        }
        CP_COMMIT();
    };

    issue_load(0, 0);
    issue_load(1, 1);
    issue_load(2, 2);
    issue_load(3, 3);

    int slot = 0;
    for (int j = 0; j < NIT; ++j) {
        CP_WAITN(3);                   // load j landed; up to 3 still flying
        __syncthreads();
        const int jn = j + 4;
        if (jn < NIT) {
            int sl = slot + 4; if (sl >= STAGES) sl -= STAGES;
            issue_load(jn, sl);
        } else {
            CP_COMMIT();               // keep group counting aligned
        }

        const uint32_t stBase = sb + slot * STAGE_BYTES;

#pragma unroll
        for (int kk = 0; kk < 2; ++kk) {
            const uint32_t kx = kk * 32;
            uint32_t bf[8][2];
#pragma unroll
            for (int nh = 0; nh < 4; ++nh) {
                uint32_t r0, r1, r2, r3;
                LDMATRIX_X4(r0, r1, r2, r3, stBase + (bOff[nh] ^ kx));
                bf[2*nh][0] = r0;   bf[2*nh][1] = r1;
                bf[2*nh+1][0] = r2; bf[2*nh+1][1] = r3;
            }
            uint32_t a[4][4];
#pragma unroll
            for (int mi = 0; mi < 4; ++mi)
                LDMATRIX_X4(a[mi][0], a[mi][1], a[mi][2], a[mi][3],
                            stBase + (aOff[mi] ^ kx));
#pragma unroll
            for (int mi = 0; mi < 4; ++mi)
#pragma unroll
                for (int ni = 0; ni < 8; ++ni)
                    MMA_F16(acc[mi][ni], a[mi][0], a[mi][1], a[mi][2], a[mi][3],
                            bf[ni][0], bf[ni][1]);
        }
        if (++slot >= STAGES) slot = 0;
    }

    // ------------------------------------------------------------ epilogue
    const int gid = lane >> 2;
    const int tig = lane & 3;

#pragma unroll
    for (int mi = 0; mi < 4; ++mi) {
        int rbase = m0 + warpM * 64 + mi * 16 + gid;
#pragma unroll
        for (int half = 0; half < 2; ++half) {
            int m = rbase + half * 8;
            float sc = (MODE == 1) ? g_scale[m] : 0.f;
#pragma unroll
            for (int ni = 0; ni < 8; ++ni) {
                int n = n0 + warpN * 64 + ni * 8 + tig * 2;
                float v0 = acc[mi][ni][half * 2 + 0];
                float v1 = acc[mi][ni][half * 2 + 1];
                if (MODE == 0) {
                    *(__half2*)&g_xi[(size_t)m * DINNER + n] =
                        __halves2half2(__float2half(v0), __float2half(v1));
                } else if (MODE == 2) {
                    float s0 = sigmoidf_(v0), s1 = sigmoidf_(v1);
                    *(__half2*)&g_gate[(size_t)m * DINNER + n] =
                        __halves2half2(__float2half(s0), __float2half(s1));
                } else {
                    *(float2*)&out[(size_t)m * DMODEL + n] = make_float2(sc * v0, sc * v1);
                }
            }
        }
    }
}

// ---------------------------------------------------------------- conv + dt (fp16 xi)
__global__ void __launch_bounds__(256) conv_dt_kernel(const float* __restrict__ conv_w,
                                                      const float* __restrict__ conv_b,
                                                      const float* __restrict__ W_dt,
                                                      const float* __restrict__ b_dt) {
    const int warp = threadIdx.x >> 5;
    const int lane = threadIdx.x & 31;
    const int m = blockIdx.x * 8 + warp;
    const int s = m & (SEQ - 1);

    float acc[16];
#pragma unroll
    for (int i = 0; i < 16; ++i) acc[i] = 0.f;

    const __half* xi_row = g_xi + (size_t)m * DINNER;

    for (int it = 0; it < DINNER / 128; ++it) {
        int e = it * 128 + lane * 4;
        float4 w0 = *(const float4*)(conv_w + (size_t)(e + 0) * 4);
        float4 w1 = *(const float4*)(conv_w + (size_t)(e + 1) * 4);
        float4 w2 = *(const float4*)(conv_w + (size_t)(e + 2) * 4);
        float4 w3 = *(const float4*)(conv_w + (size_t)(e + 3) * 4);
        float4 cb = *(const float4*)(conv_b + e);

        float4 xk[4];
#pragma unroll
        for (int k = 0; k < 4; ++k) {
            int d = 3 - k;
            if (s - d >= 0) {
                const __half2* p = (const __half2*)(xi_row - (size_t)d * DINNER + e);
                float2 lo = __half22float2(p[0]);
                float2 hi = __half22float2(p[1]);
                xk[k] = make_float4(lo.x, lo.y, hi.x, hi.y);
            } else {
                xk[k] = make_float4(0.f, 0.f, 0.f, 0.f);
            }
        }
        float4 v;
        v.x = fmaf(w0.x, xk[0].x, fmaf(w0.y, xk[1].x, fmaf(w0.z, xk[2].x, fmaf(w0.w, xk[3].x, cb.x))));
        v.y = fmaf(w1.x, xk[0].y, fmaf(w1.y, xk[1].y, fmaf(w1.z, xk[2].y, fmaf(w1.w, xk[3].y, cb.y))));
        v.z = fmaf(w2.x, xk[0].z, fmaf(w2.y, xk[1].z, fmaf(w2.z, xk[2].z, fmaf(w2.w, xk[3].z, cb.z))));
        v.w = fmaf(w3.x, xk[0].w, fmaf(w3.y, xk[1].w, fmaf(w3.z, xk[2].w, fmaf(w3.w, xk[3].w, cb.w))));

        float4 xs;
        xs.x = v.x * sigmoidf_(v.x);
        xs.y = v.y * sigmoidf_(v.y);
        xs.z = v.z * sigmoidf_(v.z);
        xs.w = v.w * sigmoidf_(v.w);

        if (it == 0 && lane < 4) {
            g_u[m * DSTATE + e + 0] = xs.x;
            g_u[m * DSTATE + e + 1] = xs.y;
            g_u[m * DSTATE + e + 2] = xs.z;
            g_u[m * DSTATE + e + 3] = xs.w;
        }
#pragma unroll
        for (int i = 0; i < 16; ++i) {
            float4 wd = *(const float4*)(W_dt + (size_t)i * DINNER + e);
            acc[i] = fmaf(xs.x, wd.x, acc[i]);
            acc[i] = fmaf(xs.y, wd.y, acc[i]);
            acc[i] = fmaf(xs.z, wd.z, acc[i]);
            acc[i] = fmaf(xs.w, wd.w, acc[i]);
        }
    }
#pragma unroll
    for (int i = 0; i < 16; ++i) {
#pragma unroll
        for (int off = 16; off > 0; off >>= 1)
            acc[i] += __shfl_xor_sync(0xffffffffu, acc[i], off);
    }
    if (lane == 0) {
#pragma unroll
        for (int i = 0; i < 16; ++i) {
            float z = acc[i] + b_dt[i];
            float sp = (z > 20.f) ? z : log1pf(expf(z));
            g_a[m * DSTATE + i] = 1.0f + sp;
        }
    }
}

// ---------------------------------------------------------------- scan
__global__ void __launch_bounds__(512) scan_kernel(const float* __restrict__ A_log) {
    const int b = blockIdx.x;
    const int tid = threadIdx.x;
    const int chunk = tid >> 4;
    const int j = tid & 15;
    const int t0 = chunk * 64;

    __shared__ float sP[32][16];
    __shared__ float sQ[32][16];
    __shared__ float sH[32][16];

    const float* a = g_a + (size_t)b * SEQ * DSTATE;
    const float* u = g_u + (size_t)b * SEQ * DSTATE;

    float P = 1.f, q = 0.f;
    for (int i = 0; i < 64; ++i) {
        float av = a[(t0 + i) * DSTATE + j];
        float uv = u[(t0 + i) * DSTATE + j];
        q = fmaf(q, av, uv);
        P *= av;
    }
    sP[chunk][j] = P;
    sQ[chunk][j] = q;
    __syncthreads();

    if (tid < 16) {
        float h = 0.f;
        for (int k = 0; k < 32; ++k) {
            sH[k][tid] = h;
            h = fmaf(sP[k][tid], h, sQ[k][tid]);
        }
    }
    __syncthreads();

    const float Aj = -expf(A_log[j]);
    float h = sH[chunk][j];
    for (int i = 0; i < 64; ++i) {
        int t = t0 + i;
        float av = a[t * DSTATE + j];
        float uv = u[t * DSTATE + j];
        h = fmaf(h, av, uv);
        float c = Aj * h;
        c += __shfl_xor_sync(0xffffffffu, c, 8, 16);
        c += __shfl_xor_sync(0xffffffffu, c, 4, 16);
        c += __shfl_xor_sync(0xffffffffu, c, 2, 16);
        c += __shfl_xor_sync(0xffffffffu, c, 1, 16);
        if (j == 0) g_scale[b * SEQ + t] = c * (float)DINNER;
    }
}

// ---------------------------------------------------------------- host
extern "C" void kernel_launch(void* const* d_in, const int* in_sizes, int n_in,
                              void* d_out, int out_size) {
    const float* x      = (const float*)d_in[0];
    const float* W_in   = (const float*)d_in[1];
    const float* conv_w = (const float*)d_in[2];
    const float* conv_b = (const float*)d_in[3];
    const float* W_dt   = (const float*)d_in[4];
    const float* b_dt   = (const float*)d_in[5];
    const float* A_log  = (const float*)d_in[6];
    const float* W_out  = (const float*)d_in[7];
    float* out = (float*)d_out;
    (void)in_sizes; (void)n_in; (void)out_size;

    void *px, *pwi, *pwo, *pg;
    cudaGetSymbolAddress(&px, g_x);
    cudaGetSymbolAddress(&pwi, g_win);
    cudaGetSymbolAddress(&pwo, g_wout);
    cudaGetSymbolAddress(&pg, g_gate);

    cudaFuncSetAttribute(gemm_mma<0, DMODEL>, cudaFuncAttributeMaxDynamicSharedMemorySize, SMEM_BYTES);
    cudaFuncSetAttribute(gemm_mma<2, DMODEL>, cudaFuncAttributeMaxDynamicSharedMemorySize, SMEM_BYTES);
    cudaFuncSetAttribute(gemm_mma<1, DINNER>, cudaFuncAttributeMaxDynamicSharedMemorySize, SMEM_BYTES);

    // fork/join objects (host-side; created per call, not freed — kernel_launch
    // only executes during correctness check + graph capture)
    cudaStream_t s2;
    cudaEvent_t evF, evJ;
    cudaStreamCreateWithFlags(&s2, cudaStreamNonBlocking);
    cudaEventCreateWithFlags(&evF, cudaEventDisableTiming);
    cudaEventCreateWithFlags(&evJ, cudaEventDisableTiming);

    // shared prerequisites on the capture (default) stream
    cvt_f16<<<(M_TOT * DMODEL / 4 + 255) / 256, 256>>>(x, (__half*)px, M_TOT * DMODEL / 4);
    cvt_f16<<<(2 * DINNER * DMODEL / 4 + 255) / 256, 256>>>(W_in, (__half*)pwi, 2 * DINNER * DMODEL / 4);

    // fork
    cudaEventRecord(evF, 0);
    cudaStreamWaitEvent(s2, evF, 0);

    // branch B (s2): W_out convert + gate half of GEMM1
    cvt_f16<<<(DMODEL * DINNER / 4 + 255) / 256, 256, 0, s2>>>(
        W_out, (__half*)pwo, DMODEL * DINNER / 4);
    gemm_mma<2, DMODEL><<<dim3(DINNER / NT, M_TOT / MT), 128, SMEM_BYTES, s2>>>(
        (const __half*)px, (const __half*)pwi + (size_t)DINNER * DMODEL, nullptr);
    cudaEventRecord(evJ, s2);

    // branch A (default stream): xi half of GEMM1 -> conv_dt -> scan
    gemm_mma<0, DMODEL><<<dim3(DINNER / NT, M_TOT / MT), 128, SMEM_BYTES>>>(
        (const __half*)px, (const __half*)pwi, nullptr);
    conv_dt_kernel<<<M_TOT / 8, 256>>>(conv_w, conv_b, W_dt, b_dt);
    scan_kernel<<<BATCH, 512>>>(A_log);

    // join, then GEMM2
    cudaStreamWaitEvent(0, evJ, 0);
    gemm_mma<1, DINNER><<<dim3(DMODEL / NT, M_TOT / MT), 128, SMEM_BYTES>>>(
        (const __half*)pg, (const __half*)pwo, out);
}

// round 17
// speedup vs baseline: 1.0608x; 1.0003x over previous
#include <cuda_runtime.h>
#include <cuda_fp16.h>
#include <math.h>
#include <cstdint>

// ---------------------------------------------------------------- constants
#define BATCH 2
#define SEQ 2048
#define DMODEL 2048
#define DINNER 4096
#define DSTATE 16
#define M_TOT (BATCH*SEQ)          // 4096

// GEMM tiling (champion): 128x128 CTA, 128 thr (4 warps x 64x64), KC=32, 5 stages
#define MT 128
#define NT 128
#define KC 32
#define STAGES 5
#define ROW_BYTES 64                               // 32 halves, swizzled
#define STAGE_ROWS 256                             // A (128) + B (128)
#define STAGE_BYTES (STAGE_ROWS * ROW_BYTES)       // 16384
#define SMEM_BYTES (STAGES * STAGE_BYTES)          // 81920

// swizzle: chunk(16B, bits[4:5]) ^= (row>>1)&3  (row stride 64B)
#define SWZ(off) ((off) ^ (((off) >> 3) & 0x30))

// ---------------------------------------------------------------- scratch
__device__ __align__(1024) __half g_xi[(size_t)M_TOT * DINNER];
__device__ __align__(1024) __half g_x[(size_t)M_TOT * DMODEL];
__device__ __align__(1024) __half g_win[(size_t)2*DINNER * DMODEL];
__device__ __align__(1024) __half g_wout[(size_t)DMODEL * DINNER];
__device__ __align__(1024) __half g_gate[(size_t)M_TOT * DINNER];
__device__ float g_a[M_TOT * DSTATE];
__device__ float g_u[M_TOT * DSTATE];
__device__ float g_scale[M_TOT];

static __device__ __forceinline__ float sigmoidf_(float v) {
    return 1.0f / (1.0f + expf(-v));
}

__device__ __forceinline__ uint32_t smem_u32(const void* p) {
    uint32_t a;
    asm("{ .reg .u64 t; cvta.to.shared.u64 t, %1; cvt.u32.u64 %0, t; }" : "=r"(a) : "l"(p));
    return a;
}

#define CP_ASYNC_16(saddr, gptr) \
    asm volatile("cp.async.cg.shared.global [%0], [%1], 16;" :: "r"(saddr), "l"(gptr))
#define CP_COMMIT() asm volatile("cp.async.commit_group;" ::: "memory")
#define CP_WAITN(n) asm volatile("cp.async.wait_group %0;" :: "n"(n) : "memory")

#define LDMATRIX_X4(r0,r1,r2,r3, addr) \
    asm volatile("ldmatrix.sync.aligned.m8n8.x4.shared.b16 {%0,%1,%2,%3}, [%4];" \
                 : "=r"(r0), "=r"(r1), "=r"(r2), "=r"(r3) : "r"(addr))

#define MMA_F16(c, a0,a1,a2,a3, b0,b1) \
    asm volatile("mma.sync.aligned.m16n8k16.row.col.f32.f16.f16.f32 " \
                 "{%0,%1,%2,%3}, {%4,%5,%6,%7}, {%8,%9}, {%0,%1,%2,%3};" \
                 : "+f"((c)[0]), "+f"((c)[1]), "+f"((c)[2]), "+f"((c)[3]) \
                 : "r"(a0), "r"(a1), "r"(a2), "r"(a3), "r"(b0), "r"(b1))

// ---------------------------------------------------------------- preprocessing
__global__ void __launch_bounds__(256) cvt_f16(const float* __restrict__ in,
                                               __half* __restrict__ o,
                                               int n4) {
    int i = blockIdx.x * 256 + threadIdx.x;
    if (i >= n4) return;
    float4 v = ((const float4*)in)[i];
    ((__half2*)o)[2*i]   = __halves2half2(__float2half(v.x), __float2half(v.y));
    ((__half2*)o)[2*i+1] = __halves2half2(__float2half(v.z), __float2half(v.w));
}

// ---------------------------------------------------------------- mma GEMM
// 128 threads, 4 warps x (64x64 warp tile), 128x128 CTA tile, 2 CTAs/SM.
// MODE 0: writes g_xi fp16 (xi half)
// MODE 2: sigmoid -> g_gate fp16 (gate half; B pre-offset by caller)
// MODE 1: out[m,n] = g_scale[m]*acc
template <int MODE, int K>
__global__ void __launch_bounds__(128, 2) gemm_mma(const __half* __restrict__ A,
                                                   const __half* __restrict__ B,
                                                   float* __restrict__ out) {
    constexpr int NIT = K / KC;

    extern __shared__ char smem[];
    const uint32_t sb = smem_u32(smem);

    const int tid  = threadIdx.x;
    const int lane = tid & 31;
    const int wid  = tid >> 5;        // 0..3
    const int warpM = wid & 1;        // 2 warps in M (64 rows each)
    const int warpN = wid >> 1;       // 2 warps in N (64 cols each)
    const int m0 = blockIdx.y * MT;
    const int n0 = blockIdx.x * NT;

    // cp.async: 1024 16B-chunks per stage, 8 per thread (swizzled dst)
    uint32_t sOff[8];
#pragma unroll
    for (int i = 0; i < 8; ++i) {
        int c   = tid + i * 128;       // 0..1023
        int row = c >> 2;              // 0..255
        uint32_t off = (uint32_t)row * ROW_BYTES + (c & 3) * 16;
        sOff[i] = SWZ(off);
    }

    // ldmatrix base offsets (kk=0); kk=1 -> XOR 32
    uint32_t aOff[4], bOff[4];
#pragma unroll
    for (int mi = 0; mi < 4; ++mi) {
        int r = warpM * 64 + mi * 16 + (lane & 15);
        uint32_t off = (uint32_t)r * ROW_BYTES + (lane >> 4) * 16;
        aOff[mi] = SWZ(off);
    }
#pragma unroll
    for (int nh = 0; nh < 4; ++nh) {
        int r = 128 + warpN * 64 + nh * 16 + ((lane >> 4) & 1) * 8 + (lane & 7);
        uint32_t off = (uint32_t)r * ROW_BYTES + ((lane >> 3) & 1) * 16;
        bOff[nh] = SWZ(off);
    }

    float acc[4][8][4];
#pragma unroll
    for (int mi = 0; mi < 4; ++mi)
#pragma unroll
        for (int ni = 0; ni < 8; ++ni)
#pragma unroll
            for (int e = 0; e < 4; ++e) acc[mi][ni][e] = 0.f;

    auto issue_load = [&](int j, int slot) {
        const int k0 = j * KC;
        const uint32_t stBase = sb + slot * STAGE_BYTES;
#pragma unroll
        for (int i = 0; i < 8; ++i) {
            int c   = tid + i * 128;
            int row = c >> 2;
            int off = (c & 3) * 8;     // halves within row
            const __half* g;
            if (i < 4) g = A + (size_t)(m0 + row)       * K + k0 + off;
            else       g = B + (size_t)(n0 + row - 128) * K + k0 + off;
            CP_ASYNC_16(stBase + sOff[i], g);
        }
        CP_COMMIT();
    };

    issue_load(0, 0);
    issue_load(1, 1);
    issue_load(2, 2);
    issue_load(3, 3);

    int slot = 0;
    for (int j = 0; j < NIT; ++j) {
        CP_WAITN(3);                   // load j landed; up to 3 still flying
        __syncthreads();
        const int jn = j + 4;
        if (jn < NIT) {
            int sl = slot + 4; if (sl >= STAGES) sl -= STAGES;
            issue_load(jn, sl);
        } else {
            CP_COMMIT();               // keep group counting aligned
        }

        const uint32_t stBase = sb + slot * STAGE_BYTES;

#pragma unroll
        for (int kk = 0; kk < 2; ++kk) {
            const uint32_t kx = kk * 32;
            uint32_t bf[8][2];
#pragma unroll
            for (int nh = 0; nh < 4; ++nh) {
                uint32_t r0, r1, r2, r3;
                LDMATRIX_X4(r0, r1, r2, r3, stBase + (bOff[nh] ^ kx));
                bf[2*nh][0] = r0;   bf[2*nh][1] = r1;
                bf[2*nh+1][0] = r2; bf[2*nh+1][1] = r3;
            }
            uint32_t a[4][4];
#pragma unroll
            for (int mi = 0; mi < 4; ++mi)
                LDMATRIX_X4(a[mi][0], a[mi][1], a[mi][2], a[mi][3],
                            stBase + (aOff[mi] ^ kx));
#pragma unroll
            for (int mi = 0; mi < 4; ++mi)
#pragma unroll
                for (int ni = 0; ni < 8; ++ni)
                    MMA_F16(acc[mi][ni], a[mi][0], a[mi][1], a[mi][2], a[mi][3],
                            bf[ni][0], bf[ni][1]);
        }
        if (++slot >= STAGES) slot = 0;
    }

    // ------------------------------------------------------------ epilogue
    const int gid = lane >> 2;
    const int tig = lane & 3;

#pragma unroll
    for (int mi = 0; mi < 4; ++mi) {
        int rbase = m0 + warpM * 64 + mi * 16 + gid;
#pragma unroll
        for (int half = 0; half < 2; ++half) {
            int m = rbase + half * 8;
            float sc = (MODE == 1) ? g_scale[m] : 0.f;
#pragma unroll
            for (int ni = 0; ni < 8; ++ni) {
                int n = n0 + warpN * 64 + ni * 8 + tig * 2;
                float v0 = acc[mi][ni][half * 2 + 0];
                float v1 = acc[mi][ni][half * 2 + 1];
                if (MODE == 0) {
                    *(__half2*)&g_xi[(size_t)m * DINNER + n] =
                        __halves2half2(__float2half(v0), __float2half(v1));
                } else if (MODE == 2) {
                    float s0 = sigmoidf_(v0), s1 = sigmoidf_(v1);
                    *(__half2*)&g_gate[(size_t)m * DINNER + n] =
                        __halves2half2(__float2half(s0), __float2half(s1));
                } else {
                    *(float2*)&out[(size_t)m * DMODEL + n] = make_float2(sc * v0, sc * v1);
                }
            }
        }
    }
}

// ---------------------------------------------------------------- conv + dt (fp16 xi)
__global__ void __launch_bounds__(256) conv_dt_kernel(const float* __restrict__ conv_w,
                                                      const float* __restrict__ conv_b,
                                                      const float* __restrict__ W_dt,
                                                      const float* __restrict__ b_dt) {
    const int warp = threadIdx.x >> 5;
    const int lane = threadIdx.x & 31;
    const int m = blockIdx.x * 8 + warp;
    const int s = m & (SEQ - 1);

    float acc[16];
#pragma unroll
    for (int i = 0; i < 16; ++i) acc[i] = 0.f;

    const __half* xi_row = g_xi + (size_t)m * DINNER;

    for (int it = 0; it < DINNER / 128; ++it) {
        int e = it * 128 + lane * 4;
        float4 w0 = *(const float4*)(conv_w + (size_t)(e + 0) * 4);
        float4 w1 = *(const float4*)(conv_w + (size_t)(e + 1) * 4);
        float4 w2 = *(const float4*)(conv_w + (size_t)(e + 2) * 4);
        float4 w3 = *(const float4*)(conv_w + (size_t)(e + 3) * 4);
        float4 cb = *(const float4*)(conv_b + e);

        float4 xk[4];
#pragma unroll
        for (int k = 0; k < 4; ++k) {
            int d = 3 - k;
            if (s - d >= 0) {
                const __half2* p = (const __half2*)(xi_row - (size_t)d * DINNER + e);
                float2 lo = __half22float2(p[0]);
                float2 hi = __half22float2(p[1]);
                xk[k] = make_float4(lo.x, lo.y, hi.x, hi.y);
            } else {
                xk[k] = make_float4(0.f, 0.f, 0.f, 0.f);
            }
        }
        float4 v;
        v.x = fmaf(w0.x, xk[0].x, fmaf(w0.y, xk[1].x, fmaf(w0.z, xk[2].x, fmaf(w0.w, xk[3].x, cb.x))));
        v.y = fmaf(w1.x, xk[0].y, fmaf(w1.y, xk[1].y, fmaf(w1.z, xk[2].y, fmaf(w1.w, xk[3].y, cb.y))));
        v.z = fmaf(w2.x, xk[0].z, fmaf(w2.y, xk[1].z, fmaf(w2.z, xk[2].z, fmaf(w2.w, xk[3].z, cb.z))));
        v.w = fmaf(w3.x, xk[0].w, fmaf(w3.y, xk[1].w, fmaf(w3.z, xk[2].w, fmaf(w3.w, xk[3].w, cb.w))));

        float4 xs;
        xs.x = v.x * sigmoidf_(v.x);
        xs.y = v.y * sigmoidf_(v.y);
        xs.z = v.z * sigmoidf_(v.z);
        xs.w = v.w * sigmoidf_(v.w);

        if (it == 0 && lane < 4) {
            g_u[m * DSTATE + e + 0] = xs.x;
            g_u[m * DSTATE + e + 1] = xs.y;
            g_u[m * DSTATE + e + 2] = xs.z;
            g_u[m * DSTATE + e + 3] = xs.w;
        }
#pragma unroll
        for (int i = 0; i < 16; ++i) {
            float4 wd = *(const float4*)(W_dt + (size_t)i * DINNER + e);
            acc[i] = fmaf(xs.x, wd.x, acc[i]);
            acc[i] = fmaf(xs.y, wd.y, acc[i]);
            acc[i] = fmaf(xs.z, wd.z, acc[i]);
            acc[i] = fmaf(xs.w, wd.w, acc[i]);
        }
    }
#pragma unroll
    for (int i = 0; i < 16; ++i) {
#pragma unroll
        for (int off = 16; off > 0; off >>= 1)
            acc[i] += __shfl_xor_sync(0xffffffffu, acc[i], off);
    }
    if (lane == 0) {
#pragma unroll
        for (int i = 0; i < 16; ++i) {
            float z = acc[i] + b_dt[i];
            float sp = (z > 20.f) ? z : log1pf(expf(z));
            g_a[m * DSTATE + i] = 1.0f + sp;
        }
    }
}

// ---------------------------------------------------------------- scan
__global__ void __launch_bounds__(512) scan_kernel(const float* __restrict__ A_log) {
    const int b = blockIdx.x;
    const int tid = threadIdx.x;
    const int chunk = tid >> 4;
    const int j = tid & 15;
    const int t0 = chunk * 64;

    __shared__ float sP[32][16];
    __shared__ float sQ[32][16];
    __shared__ float sH[32][16];

    const float* a = g_a + (size_t)b * SEQ * DSTATE;
    const float* u = g_u + (size_t)b * SEQ * DSTATE;

    float P = 1.f, q = 0.f;
    for (int i = 0; i < 64; ++i) {
        float av = a[(t0 + i) * DSTATE + j];
        float uv = u[(t0 + i) * DSTATE + j];
        q = fmaf(q, av, uv);
        P *= av;
    }
    sP[chunk][j] = P;
    sQ[chunk][j] = q;
    __syncthreads();

    if (tid < 16) {
        float h = 0.f;
        for (int k = 0; k < 32; ++k) {
            sH[k][tid] = h;
            h = fmaf(sP[k][tid], h, sQ[k][tid]);
        }
    }
    __syncthreads();

    const float Aj = -expf(A_log[j]);
    float h = sH[chunk][j];
    for (int i = 0; i < 64; ++i) {
        int t = t0 + i;
        float av = a[t * DSTATE + j];
        float uv = u[t * DSTATE + j];
        h = fmaf(h, av, uv);
        float c = Aj * h;
        c += __shfl_xor_sync(0xffffffffu, c, 8, 16);
        c += __shfl_xor_sync(0xffffffffu, c, 4, 16);
        c += __shfl_xor_sync(0xffffffffu, c, 2, 16);
        c += __shfl_xor_sync(0xffffffffu, c, 1, 16);
        if (j == 0) g_scale[b * SEQ + t] = c * (float)DINNER;
    }
}

// ---------------------------------------------------------------- host
extern "C" void kernel_launch(void* const* d_in, const int* in_sizes, int n_in,
                              void* d_out, int out_size) {
    const float* x      = (const float*)d_in[0];
    const float* W_in   = (const float*)d_in[1];
    const float* conv_w = (const float*)d_in[2];
    const float* conv_b = (const float*)d_in[3];
    const float* W_dt   = (const float*)d_in[4];
    const float* b_dt   = (const float*)d_in[5];
    const float* A_log  = (const float*)d_in[6];
    const float* W_out  = (const float*)d_in[7];
    float* out = (float*)d_out;
    (void)in_sizes; (void)n_in; (void)out_size;

    void *px, *pwi, *pwo, *pg;
    cudaGetSymbolAddress(&px, g_x);
    cudaGetSymbolAddress(&pwi, g_win);
    cudaGetSymbolAddress(&pwo, g_wout);
    cudaGetSymbolAddress(&pg, g_gate);

    cudaFuncSetAttribute(gemm_mma<0, DMODEL>, cudaFuncAttributeMaxDynamicSharedMemorySize, SMEM_BYTES);
    cudaFuncSetAttribute(gemm_mma<2, DMODEL>, cudaFuncAttributeMaxDynamicSharedMemorySize, SMEM_BYTES);
    cudaFuncSetAttribute(gemm_mma<1, DINNER>, cudaFuncAttributeMaxDynamicSharedMemorySize, SMEM_BYTES);

    // fork/join objects (host-side; created per call, not freed — kernel_launch
    // only executes during correctness check + graph capture)
    cudaStream_t s2;
    cudaEvent_t evF, evJ;
    cudaStreamCreateWithFlags(&s2, cudaStreamNonBlocking);
    cudaEventCreateWithFlags(&evF, cudaEventDisableTiming);
    cudaEventCreateWithFlags(&evJ, cudaEventDisableTiming);

    const int W_HALF_ELEMS = DINNER * DMODEL;      // one half of W_in (elements)

    // shared prerequisite: only x conversion
    cvt_f16<<<(M_TOT * DMODEL / 4 + 255) / 256, 256>>>(x, (__half*)px, M_TOT * DMODEL / 4);

    // fork
    cudaEventRecord(evF, 0);
    cudaStreamWaitEvent(s2, evF, 0);

    // branch B (s2): convert gate half of W_in + W_out, then gate half of GEMM1
    cvt_f16<<<(W_HALF_ELEMS / 4 + 255) / 256, 256, 0, s2>>>(
        W_in + (size_t)W_HALF_ELEMS, (__half*)pwi + (size_t)W_HALF_ELEMS, W_HALF_ELEMS / 4);
    cvt_f16<<<(W_HALF_ELEMS / 4 + 255) / 256, 256, 0, s2>>>(
        W_out, (__half*)pwo, W_HALF_ELEMS / 4);
    gemm_mma<2, DMODEL><<<dim3(DINNER / NT, M_TOT / MT), 128, SMEM_BYTES, s2>>>(
        (const __half*)px, (const __half*)pwi + (size_t)W_HALF_ELEMS, nullptr);
    cudaEventRecord(evJ, s2);

    // branch A (default stream): convert xi half of W_in, xi half of GEMM1,
    // then conv_dt and scan
    cvt_f16<<<(W_HALF_ELEMS / 4 + 255) / 256, 256>>>(
        W_in, (__half*)pwi, W_HALF_ELEMS / 4);
    gemm_mma<0, DMODEL><<<dim3(DINNER / NT, M_TOT / MT), 128, SMEM_BYTES>>>(
        (const __half*)px, (const __half*)pwi, nullptr);
    conv_dt_kernel<<<M_TOT / 8, 256>>>(conv_w, conv_b, W_dt, b_dt);
    scan_kernel<<<BATCH, 512>>>(A_log);

    // join, then GEMM2
    cudaStreamWaitEvent(0, evJ, 0);
    gemm_mma<1, DINNER><<<dim3(DMODEL / NT, M_TOT / MT), 128, SMEM_BYTES>>>(
        (const __half*)pg, (const __half*)pwo, out);
}